// round 1
// baseline (speedup 1.0000x reference)
#include <cuda_runtime.h>
#include <math.h>

// ---------------- problem constants ----------------
#define T_TOK   8192
#define DIM     2048
#define NH      16
#define NKV     8
#define HD      128
#define S_LEN   1024
#define B_SZ    8
#define KV_DIM  1024      // NKV * HD
#define N_REP   2

// ---------------- scratch ----------------
__device__ float g_q[T_TOK * DIM];
__device__ float g_k[T_TOK * KV_DIM];
__device__ float g_v[T_TOK * KV_DIM];
__device__ float g_attn[T_TOK * DIM];

// ---------------- SGEMM: C[M,N] = A[M,K] @ B[K,N], all row-major ----------------
// 128x128 block tile, K-tile 8, 256 threads, 8x8 per-thread microtile
// (split-fragment layout: rows {ty*4..+3, 64+ty*4..+3}, cols {tx*4..+3, 64+tx*4..+3})
__global__ __launch_bounds__(256, 2)
void sgemm128(const float* __restrict__ A, const float* __restrict__ B,
              float* __restrict__ C, int M, int N, int K)
{
    __shared__ float As[8][128];   // transposed A tile
    __shared__ float Bs[8][128];

    const int tid = threadIdx.x;
    const int bx = blockIdx.x;     // N tile
    const int by = blockIdx.y;     // M tile
    const int tx = tid & 15;
    const int ty = tid >> 4;

    const float* Ab = A + (size_t)(by * 128) * K;
    const float* Bb = B + (size_t)bx * 128;

    const int a_r = tid >> 1;           // 0..127
    const int a_c = (tid & 1) << 2;     // 0 or 4
    const int b_r = tid >> 5;           // 0..7
    const int b_c = (tid & 31) << 2;    // 0..124

    float acc[8][8];
#pragma unroll
    for (int i = 0; i < 8; i++)
#pragma unroll
        for (int j = 0; j < 8; j++) acc[i][j] = 0.f;

    for (int k0 = 0; k0 < K; k0 += 8) {
        float4 av = *(const float4*)(Ab + (size_t)a_r * K + k0 + a_c);
        float4 bv = *(const float4*)(Bb + (size_t)(k0 + b_r) * N + b_c);
        As[a_c + 0][a_r] = av.x;
        As[a_c + 1][a_r] = av.y;
        As[a_c + 2][a_r] = av.z;
        As[a_c + 3][a_r] = av.w;
        *(float4*)(&Bs[b_r][b_c]) = bv;
        __syncthreads();

#pragma unroll
        for (int kk = 0; kk < 8; kk++) {
            float a[8], b[8];
            *(float4*)(a)     = *(const float4*)(&As[kk][ty * 4]);
            *(float4*)(a + 4) = *(const float4*)(&As[kk][64 + ty * 4]);
            *(float4*)(b)     = *(const float4*)(&Bs[kk][tx * 4]);
            *(float4*)(b + 4) = *(const float4*)(&Bs[kk][64 + tx * 4]);
#pragma unroll
            for (int i = 0; i < 8; i++)
#pragma unroll
                for (int j = 0; j < 8; j++)
                    acc[i][j] += a[i] * b[j];
        }
        __syncthreads();
    }

#pragma unroll
    for (int i = 0; i < 8; i++) {
        int r = by * 128 + ((i < 4) ? (ty * 4 + i) : (64 + ty * 4 + i - 4));
        float* Crow = C + (size_t)r * N + bx * 128;
        *(float4*)(Crow + tx * 4)      = make_float4(acc[i][0], acc[i][1], acc[i][2], acc[i][3]);
        *(float4*)(Crow + 64 + tx * 4) = make_float4(acc[i][4], acc[i][5], acc[i][6], acc[i][7]);
    }
}

// ---------------- RoPE (in place). x: [T, n_heads*HD], interleaved pairs ----------------
__global__ __launch_bounds__(256)
void rope_kernel(float* __restrict__ x, const int* __restrict__ positions, int n_heads, int total)
{
    int idx = blockIdx.x * blockDim.x + threadIdx.x;
    if (idx >= total) return;
    int pair = idx & 63;                  // HD/2 = 64
    int h    = (idx >> 6) % n_heads;
    int t    = idx / (64 * n_heads);
    // accurate angle/trig: double, matches fp32 reference to well under tolerance
    double inv = pow(10000.0, -(double)(2 * pair) / 128.0);
    double ang = (double)positions[t] * inv;
    float c = (float)cos(ang);
    float s = (float)sin(ang);
    float* p = x + (size_t)t * (n_heads * HD) + h * HD + 2 * pair;
    float xr = p[0], xi = p[1];
    p[0] = xr * c - xi * s;
    p[1] = xr * s + xi * c;
}

// ---------------- flash attention (causal, GQA rep=2) ----------------
// grid: (S/64 q-tiles, NH, B), 128 threads
// smem: Qs[64][129] | KVs[64][129] (K phase, stride 129) / [64][128] (V phase) | Ps[64][65]
#define BQ 64
#define BK 64
#define QS_STRIDE 129
#define PS_STRIDE 65
#define ATT_SMEM_FLOATS (2 * 64 * 129 + 64 * 65)

__global__ __launch_bounds__(128, 2)
void attn_kernel(const float* __restrict__ q, const float* __restrict__ k,
                 const float* __restrict__ v, float* __restrict__ o)
{
    extern __shared__ float sm[];
    float* Qs  = sm;                     // [64][129]
    float* KVs = sm + 64 * QS_STRIDE;    // [64][129] or [64][128]
    float* Ps  = sm + 2 * 64 * QS_STRIDE;// [64][65]

    const int tid = threadIdx.x;
    const int tx = tid & 7;    // 0..7  (score cols tx*8..+7; O cols g*32+tx*4..+3)
    const int ty = tid >> 3;   // 0..15 (rows ty*4..+3)
    const int qt = blockIdx.x;
    const int h  = blockIdx.y;
    const int b  = blockIdx.z;
    const int kvh = h >> 1;    // N_REP = 2
    const int q0 = qt * BQ;

    const float scale = 0.08838834764831845f;  // 1/sqrt(128)

    // load Q tile (scaled)
    {
        const float* qbase = q + ((size_t)(b * S_LEN + q0)) * DIM + h * HD;
        for (int idx = tid; idx < BQ * HD; idx += 128) {
            int r = idx >> 7;
            int d = idx & 127;
            Qs[r * QS_STRIDE + d] = qbase[(size_t)r * DIM + d] * scale;
        }
    }

    float O[4][16];
    float m_i[4], l_i[4];
#pragma unroll
    for (int i = 0; i < 4; i++) {
        m_i[i] = -1e30f;
        l_i[i] = 0.f;
#pragma unroll
        for (int c = 0; c < 16; c++) O[i][c] = 0.f;
    }

    const int n_tiles = qt + 1;   // causal: key tiles 0..qt
    for (int kt = 0; kt < n_tiles; kt++) {
        const int k0 = kt * BK;
        __syncthreads();   // prev iteration's readers of KVs/Ps done (and Qs ready on iter 0)

        // load K tile, stride 129
        {
            const float* kbase = k + ((size_t)(b * S_LEN + k0)) * KV_DIM + kvh * HD;
            for (int idx = tid; idx < BK * HD; idx += 128) {
                int r = idx >> 7;
                int d = idx & 127;
                KVs[r * QS_STRIDE + d] = kbase[(size_t)r * KV_DIM + d];
            }
        }
        __syncthreads();

        // scores s[4][8] = Q rows (ty*4+i) . K rows (tx*8+j)
        float s[4][8];
#pragma unroll
        for (int i = 0; i < 4; i++)
#pragma unroll
            for (int j = 0; j < 8; j++) s[i][j] = 0.f;

#pragma unroll 4
        for (int d = 0; d < HD; d++) {
            float qv[4], kv[8];
#pragma unroll
            for (int i = 0; i < 4; i++) qv[i] = Qs[(ty * 4 + i) * QS_STRIDE + d];
#pragma unroll
            for (int j = 0; j < 8; j++) kv[j] = KVs[(tx * 8 + j) * QS_STRIDE + d];
#pragma unroll
            for (int i = 0; i < 4; i++)
#pragma unroll
                for (int j = 0; j < 8; j++)
                    s[i][j] += qv[i] * kv[j];
        }

        // causal mask (only diagonal tile needs it: kt == qt)
        if (kt == qt) {
#pragma unroll
            for (int i = 0; i < 4; i++) {
                int qpos = q0 + ty * 4 + i;
#pragma unroll
                for (int j = 0; j < 8; j++) {
                    int kpos = k0 + tx * 8 + j;
                    if (kpos > qpos) s[i][j] = -1e30f;
                }
            }
        }

        // online softmax
        float mnew[4], alpha[4], psum[4];
#pragma unroll
        for (int i = 0; i < 4; i++) {
            float mx = s[i][0];
#pragma unroll
            for (int j = 1; j < 8; j++) mx = fmaxf(mx, s[i][j]);
#pragma unroll
            for (int off = 1; off < 8; off <<= 1)
                mx = fmaxf(mx, __shfl_xor_sync(0xffffffffu, mx, off));
            mnew[i] = fmaxf(m_i[i], mx);
            alpha[i] = expf(m_i[i] - mnew[i]);
            float ps = 0.f;
#pragma unroll
            for (int j = 0; j < 8; j++) {
                float p = expf(s[i][j] - mnew[i]);
                s[i][j] = p;
                ps += p;
            }
#pragma unroll
            for (int off = 1; off < 8; off <<= 1)
                ps += __shfl_xor_sync(0xffffffffu, ps, off);
            l_i[i] = l_i[i] * alpha[i] + ps;
            m_i[i] = mnew[i];
#pragma unroll
            for (int c = 0; c < 16; c++) O[i][c] *= alpha[i];
        }

        // stage P transposed: Ps[col][row]
#pragma unroll
        for (int j = 0; j < 8; j++)
#pragma unroll
            for (int i = 0; i < 4; i++)
                Ps[(tx * 8 + j) * PS_STRIDE + (ty * 4 + i)] = s[i][j];
        __syncthreads();   // K reads done, P visible

        // load V tile into KVs, stride 128 (aligned for float4 reads)
        {
            const float* vbase = v + ((size_t)(b * S_LEN + k0)) * KV_DIM + kvh * HD;
            for (int idx = tid; idx < BK * HD; idx += 128) {
                int r = idx >> 7;
                int d = idx & 127;
                KVs[r * 128 + d] = vbase[(size_t)r * KV_DIM + d];
            }
        }
        __syncthreads();

        // O += P @ V
#pragma unroll 2
        for (int j = 0; j < BK; j++) {
            float pv[4];
#pragma unroll
            for (int i = 0; i < 4; i++) pv[i] = Ps[j * PS_STRIDE + ty * 4 + i];
#pragma unroll
            for (int g = 0; g < 4; g++) {
                float4 vv = *(const float4*)(&KVs[j * 128 + g * 32 + tx * 4]);
#pragma unroll
                for (int i = 0; i < 4; i++) {
                    O[i][g * 4 + 0] += pv[i] * vv.x;
                    O[i][g * 4 + 1] += pv[i] * vv.y;
                    O[i][g * 4 + 2] += pv[i] * vv.z;
                    O[i][g * 4 + 3] += pv[i] * vv.w;
                }
            }
        }
    }

    // normalize and write
#pragma unroll
    for (int i = 0; i < 4; i++) {
        float inv_l = 1.f / l_i[i];
        int t = b * S_LEN + q0 + ty * 4 + i;
        float* orow = o + (size_t)t * DIM + h * HD;
#pragma unroll
        for (int g = 0; g < 4; g++) {
            float4 st = make_float4(O[i][g * 4 + 0] * inv_l, O[i][g * 4 + 1] * inv_l,
                                    O[i][g * 4 + 2] * inv_l, O[i][g * 4 + 3] * inv_l);
            *(float4*)(&orow[g * 32 + tx * 4]) = st;
        }
    }
}

// ---------------- launcher ----------------
extern "C" void kernel_launch(void* const* d_in, const int* in_sizes, int n_in,
                              void* d_out, int out_size)
{
    const float* x  = (const float*)d_in[0];
    const float* wq = (const float*)d_in[1];
    const float* wk = (const float*)d_in[2];
    const float* wv = (const float*)d_in[3];
    const float* wo = (const float*)d_in[4];
    const int* positions = (const int*)d_in[7];
    float* out = (float*)d_out;

    float *pq, *pk, *pv, *pa;
    cudaGetSymbolAddress((void**)&pq, g_q);
    cudaGetSymbolAddress((void**)&pk, g_k);
    cudaGetSymbolAddress((void**)&pv, g_v);
    cudaGetSymbolAddress((void**)&pa, g_attn);

    // QKV projections
    sgemm128<<<dim3(DIM / 128,    T_TOK / 128), 256>>>(x, wq, pq, T_TOK, DIM,    DIM);
    sgemm128<<<dim3(KV_DIM / 128, T_TOK / 128), 256>>>(x, wk, pk, T_TOK, KV_DIM, DIM);
    sgemm128<<<dim3(KV_DIM / 128, T_TOK / 128), 256>>>(x, wv, pv, T_TOK, KV_DIM, DIM);

    // RoPE on q and k
    {
        int total_q = T_TOK * NH * (HD / 2);
        int total_k = T_TOK * NKV * (HD / 2);
        rope_kernel<<<(total_q + 255) / 256, 256>>>(pq, positions, NH,  total_q);
        rope_kernel<<<(total_k + 255) / 256, 256>>>(pk, positions, NKV, total_k);
    }

    // attention
    {
        size_t smem = ATT_SMEM_FLOATS * sizeof(float);   // 82688 B
        cudaFuncSetAttribute(attn_kernel, cudaFuncAttributeMaxDynamicSharedMemorySize, (int)smem);
        attn_kernel<<<dim3(S_LEN / BQ, NH, B_SZ), 128, smem>>>(pq, pk, pv, pa);
    }

    // output projection
    sgemm128<<<dim3(DIM / 128, T_TOK / 128), 256>>>(pa, wo, out, T_TOK, DIM, DIM);
}

// round 4
// speedup vs baseline: 1.4103x; 1.4103x over previous
#include <cuda_runtime.h>
#include <cuda_bf16.h>
#include <cstdint>
#include <math.h>

// ---------------- problem constants ----------------
#define T_TOK   8192
#define DIM     2048
#define NH      16
#define NKV     8
#define HD      128
#define S_LEN   1024
#define B_SZ    8
#define KV_DIM  1024      // NKV * HD
#define N_REP   2

// ---------------- scratch ----------------
__device__ float g_q[T_TOK * DIM];
__device__ float g_k[T_TOK * KV_DIM];
__device__ float g_v[T_TOK * KV_DIM];
__device__ float g_attn[T_TOK * DIM];

// bf16 hi/lo splits of activations
__device__ __nv_bfloat16 g_xh[T_TOK * DIM];
__device__ __nv_bfloat16 g_xl[T_TOK * DIM];
__device__ __nv_bfloat16 g_ah[T_TOK * DIM];
__device__ __nv_bfloat16 g_al[T_TOK * DIM];
// transposed bf16 hi/lo weights: [N, K] row-major (K contiguous)
__device__ __nv_bfloat16 g_wqTh[DIM * DIM];
__device__ __nv_bfloat16 g_wqTl[DIM * DIM];
__device__ __nv_bfloat16 g_wkTh[KV_DIM * DIM];
__device__ __nv_bfloat16 g_wkTl[KV_DIM * DIM];
__device__ __nv_bfloat16 g_wvTh[KV_DIM * DIM];
__device__ __nv_bfloat16 g_wvTl[KV_DIM * DIM];
__device__ __nv_bfloat16 g_woTh[DIM * DIM];
__device__ __nv_bfloat16 g_woTl[DIM * DIM];

// ================= low-level helpers (sm_80-class PTX only) =================
__device__ __forceinline__ uint32_t smem_to_u32(const void* smem_ptr) {
    uint32_t addr;
    asm("{ .reg .u64 tmp; cvta.to.shared.u64 tmp, %1; cvt.u32.u64 %0, tmp; }"
        : "=r"(addr) : "l"(smem_ptr));
    return addr;
}

#define CP_ASYNC16(dst_u32, src_ptr) \
    asm volatile("cp.async.cg.shared.global [%0], [%1], 16;" \
                 :: "r"(dst_u32), "l"(src_ptr) : "memory")
#define CP_COMMIT() asm volatile("cp.async.commit_group;" ::: "memory")
#define CP_WAIT0()  asm volatile("cp.async.wait_group 0;" ::: "memory")
#define CP_WAIT1()  asm volatile("cp.async.wait_group 1;" ::: "memory")

__device__ __forceinline__ void ldm_x4(uint32_t* r, uint32_t addr) {
    asm volatile("ldmatrix.sync.aligned.m8n8.x4.shared.b16 {%0,%1,%2,%3}, [%4];"
                 : "=r"(r[0]), "=r"(r[1]), "=r"(r[2]), "=r"(r[3]) : "r"(addr));
}
__device__ __forceinline__ void ldm_x2(uint32_t* r, uint32_t addr) {
    asm volatile("ldmatrix.sync.aligned.m8n8.x2.shared.b16 {%0,%1}, [%2];"
                 : "=r"(r[0]), "=r"(r[1]) : "r"(addr));
}
__device__ __forceinline__ void mma16816(float* c, const uint32_t* a, const uint32_t* b) {
    asm volatile("mma.sync.aligned.m16n8k16.row.col.f32.bf16.bf16.f32 "
                 "{%0,%1,%2,%3}, {%4,%5,%6,%7}, {%8,%9}, {%0,%1,%2,%3};"
                 : "+f"(c[0]), "+f"(c[1]), "+f"(c[2]), "+f"(c[3])
                 : "r"(a[0]), "r"(a[1]), "r"(a[2]), "r"(a[3]), "r"(b[0]), "r"(b[1]));
}

// ================= bf16x3 mma.sync GEMM =================
// C[M,N] = A[M,K] @ W[K,N];  A as (Ah+Al) bf16 [M,K] K-major,
// W^T as (Bh+Bl) bf16 [N,K] K-major.  CTA tile 128x128, K-tile 32, 2-stage cp.async.
//
// smem tile layout: 128 rows x 80 bytes (32 bf16 used + 8 pad). 80B stride makes
// both cp.async stores and ldmatrix row-sets bank-conflict-free and 16B-aligned.
#define GT_ROWB   80
#define GT_TILE   (128 * GT_ROWB)          // 10240 B
#define GT_STAGE  (4 * GT_TILE)            // Ah,Al,Bh,Bl = 40960 B
#define GT_TOTAL  (2 * GT_STAGE)           // 81920 B

__global__ __launch_bounds__(256, 2)
void gemm_mma(const __nv_bfloat16* __restrict__ Ah, const __nv_bfloat16* __restrict__ Al,
              const __nv_bfloat16* __restrict__ Bh, const __nv_bfloat16* __restrict__ Bl,
              float* __restrict__ C, int Ncols, int K)
{
    extern __shared__ char smc[];
    const uint32_t sbase = smem_to_u32(smc);

    const int tid  = threadIdx.x;
    const int lane = tid & 31;
    const int wid  = tid >> 5;
    const int bx = blockIdx.x;   // N tile
    const int by = blockIdx.y;   // M tile
    const int m0 = (wid & 1) * 64;    // warp M offset in CTA tile
    const int n0 = (wid >> 1) * 32;   // warp N offset

    // --- load mapping: 512 16B-chunks per tile, 2 per thread ---
    const int ch0 = tid;           // chunk = row*4 + c
    const int ch1 = tid + 256;
    const int r0c = ch0 >> 2, c0c = ch0 & 3;
    const int r1c = ch1 >> 2, c1c = ch1 & 3;

    const size_t ga0 = (size_t)(by * 128 + r0c) * K + c0c * 8;
    const size_t ga1 = (size_t)(by * 128 + r1c) * K + c1c * 8;
    const size_t gb0 = (size_t)(bx * 128 + r0c) * K + c0c * 8;
    const size_t gb1 = (size_t)(bx * 128 + r1c) * K + c1c * 8;
    const uint32_t so0 = r0c * GT_ROWB + c0c * 16;
    const uint32_t so1 = r1c * GT_ROWB + c1c * 16;

    float acc[4][4][4];
#pragma unroll
    for (int i = 0; i < 4; i++)
#pragma unroll
        for (int j = 0; j < 4; j++)
#pragma unroll
            for (int e = 0; e < 4; e++) acc[i][j][e] = 0.f;

    const int n_kt = K >> 5;

    // ldmatrix addresses (within a tile), per k16 step handled by +32B col offset
    const uint32_t a_row = (uint32_t)(m0 + (lane & 15));
    const uint32_t a_coloff = (uint32_t)((lane >> 4) * 16);       // bytes
    const uint32_t b_row = (uint32_t)(n0 + (lane & 7));
    const uint32_t b_coloff = (uint32_t)(((lane >> 3) & 1) * 16); // bytes (lanes 0-15 matter)

    // prologue: stage 0
    {
        const uint32_t st = sbase;
        CP_ASYNC16(st + 0 * GT_TILE + so0, Ah + ga0);
        CP_ASYNC16(st + 0 * GT_TILE + so1, Ah + ga1);
        CP_ASYNC16(st + 1 * GT_TILE + so0, Al + ga0);
        CP_ASYNC16(st + 1 * GT_TILE + so1, Al + ga1);
        CP_ASYNC16(st + 2 * GT_TILE + so0, Bh + gb0);
        CP_ASYNC16(st + 2 * GT_TILE + so1, Bh + gb1);
        CP_ASYNC16(st + 3 * GT_TILE + so0, Bl + gb0);
        CP_ASYNC16(st + 3 * GT_TILE + so1, Bl + gb1);
        CP_COMMIT();
    }

    for (int kt = 0; kt < n_kt; kt++) {
        const int cur = kt & 1;
        if (kt + 1 < n_kt) {
            const uint32_t st = sbase + (cur ^ 1) * GT_STAGE;
            const size_t ko = (size_t)(kt + 1) * 32;
            CP_ASYNC16(st + 0 * GT_TILE + so0, Ah + ga0 + ko);
            CP_ASYNC16(st + 0 * GT_TILE + so1, Ah + ga1 + ko);
            CP_ASYNC16(st + 1 * GT_TILE + so0, Al + ga0 + ko);
            CP_ASYNC16(st + 1 * GT_TILE + so1, Al + ga1 + ko);
            CP_ASYNC16(st + 2 * GT_TILE + so0, Bh + gb0 + ko);
            CP_ASYNC16(st + 2 * GT_TILE + so1, Bh + gb1 + ko);
            CP_ASYNC16(st + 3 * GT_TILE + so0, Bl + gb0 + ko);
            CP_ASYNC16(st + 3 * GT_TILE + so1, Bl + gb1 + ko);
            CP_COMMIT();
            CP_WAIT1();
        } else {
            CP_WAIT0();
        }
        __syncthreads();

        const uint32_t st = sbase + cur * GT_STAGE;
        const uint32_t sAh = st;
        const uint32_t sAl = st + 1 * GT_TILE;
        const uint32_t sBh = st + 2 * GT_TILE;
        const uint32_t sBl = st + 3 * GT_TILE;

#pragma unroll
        for (int ks = 0; ks < 2; ks++) {
            const uint32_t kb = ks * 32;   // 16 bf16 = 32 bytes

            uint32_t ah[4][4], bh[4][2], bl[4][2];
#pragma unroll
            for (int mt = 0; mt < 4; mt++)
                ldm_x4(ah[mt], sAh + (a_row + mt * 16) * GT_ROWB + kb + a_coloff);
#pragma unroll
            for (int nt = 0; nt < 4; nt++) {
                ldm_x2(bh[nt], sBh + (b_row + nt * 8) * GT_ROWB + kb + b_coloff);
                ldm_x2(bl[nt], sBl + (b_row + nt * 8) * GT_ROWB + kb + b_coloff);
            }
            // pass 1: Ahi * Bhi ; pass 2: Ahi * Blo
#pragma unroll
            for (int mt = 0; mt < 4; mt++)
#pragma unroll
                for (int nt = 0; nt < 4; nt++) {
                    mma16816(acc[mt][nt], ah[mt], bh[nt]);
                    mma16816(acc[mt][nt], ah[mt], bl[nt]);
                }
            // pass 3: Alo * Bhi (reuse ah regs)
#pragma unroll
            for (int mt = 0; mt < 4; mt++)
                ldm_x4(ah[mt], sAl + (a_row + mt * 16) * GT_ROWB + kb + a_coloff);
#pragma unroll
            for (int mt = 0; mt < 4; mt++)
#pragma unroll
                for (int nt = 0; nt < 4; nt++)
                    mma16816(acc[mt][nt], ah[mt], bh[nt]);
        }
        __syncthreads();
    }

    // epilogue: acc tile (mt,nt): rows by*128+m0+mt*16+{g, g+8}, cols bx*128+n0+nt*8+tg*2
    const int g  = lane >> 2;
    const int tg = (lane & 3) * 2;
#pragma unroll
    for (int mt = 0; mt < 4; mt++) {
        const int r = by * 128 + m0 + mt * 16 + g;
#pragma unroll
        for (int nt = 0; nt < 4; nt++) {
            const int cc = bx * 128 + n0 + nt * 8 + tg;
            *(float2*)(C + (size_t)r * Ncols + cc) =
                make_float2(acc[mt][nt][0], acc[mt][nt][1]);
            *(float2*)(C + (size_t)(r + 8) * Ncols + cc) =
                make_float2(acc[mt][nt][2], acc[mt][nt][3]);
        }
    }
}

// ---------------- fp32 -> bf16 hi/lo split ----------------
__global__ __launch_bounds__(256)
void convert_split(const float* __restrict__ X, __nv_bfloat16* __restrict__ H,
                   __nv_bfloat16* __restrict__ L, int total)
{
    int i = blockIdx.x * blockDim.x + threadIdx.x;
    if (i >= total) return;
    float v = X[i];
    __nv_bfloat16 h = __float2bfloat16(v);
    H[i] = h;
    L[i] = __float2bfloat16(v - __bfloat162float(h));
}

// ---------------- W[K,N] -> W^T hi/lo bf16 [N,K] ----------------
__global__ __launch_bounds__(256)
void transpose_convert(const float* __restrict__ W, __nv_bfloat16* __restrict__ Th,
                       __nv_bfloat16* __restrict__ Tl, int K, int N)
{
    __shared__ float t[32][33];
    int n0 = blockIdx.x * 32, k0 = blockIdx.y * 32;
    int tx = threadIdx.x & 31, ty = threadIdx.x >> 5;   // 32x8
#pragma unroll
    for (int j = 0; j < 4; j++)
        t[ty + j * 8][tx] = W[(size_t)(k0 + ty + j * 8) * N + n0 + tx];
    __syncthreads();
#pragma unroll
    for (int j = 0; j < 4; j++) {
        float v = t[tx][ty + j * 8];
        __nv_bfloat16 h = __float2bfloat16(v);
        __nv_bfloat16 l = __float2bfloat16(v - __bfloat162float(h));
        size_t o = (size_t)(n0 + ty + j * 8) * K + k0 + tx;
        Th[o] = h;
        Tl[o] = l;
    }
}

// ---------------- RoPE (in place). x: [T, n_heads*HD], interleaved pairs ----------------
__global__ __launch_bounds__(256)
void rope_kernel(float* __restrict__ x, const int* __restrict__ positions, int n_heads, int total)
{
    int idx = blockIdx.x * blockDim.x + threadIdx.x;
    if (idx >= total) return;
    int pair = idx & 63;                  // HD/2 = 64
    int h    = (idx >> 6) % n_heads;
    int t    = idx / (64 * n_heads);
    double inv = pow(10000.0, -(double)(2 * pair) / 128.0);
    double ang = (double)positions[t] * inv;
    float c = (float)cos(ang);
    float s = (float)sin(ang);
    float* p = x + (size_t)t * (n_heads * HD) + h * HD + 2 * pair;
    float xr = p[0], xi = p[1];
    p[0] = xr * c - xi * s;
    p[1] = xr * s + xi * c;
}

// ---------------- flash attention (causal, GQA rep=2) ----------------
#define BQ 64
#define BK 64
#define QS_STRIDE 129
#define PS_STRIDE 65
#define ATT_SMEM_FLOATS (2 * 64 * 129 + 64 * 65)

__global__ __launch_bounds__(128, 2)
void attn_kernel(const float* __restrict__ q, const float* __restrict__ k,
                 const float* __restrict__ v, float* __restrict__ o)
{
    extern __shared__ float smf[];
    float* Qs  = smf;
    float* KVs = smf + 64 * QS_STRIDE;
    float* Ps  = smf + 2 * 64 * QS_STRIDE;

    const int tid = threadIdx.x;
    const int tx = tid & 7;
    const int ty = tid >> 3;
    const int qt = blockIdx.x;
    const int h  = blockIdx.y;
    const int b  = blockIdx.z;
    const int kvh = h >> 1;
    const int q0 = qt * BQ;

    const float scale = 0.08838834764831845f;

    {
        const float* qbase = q + ((size_t)(b * S_LEN + q0)) * DIM + h * HD;
        for (int idx = tid; idx < BQ * HD; idx += 128) {
            int r = idx >> 7;
            int d = idx & 127;
            Qs[r * QS_STRIDE + d] = qbase[(size_t)r * DIM + d] * scale;
        }
    }

    float O[4][16];
    float m_i[4], l_i[4];
#pragma unroll
    for (int i = 0; i < 4; i++) {
        m_i[i] = -1e30f;
        l_i[i] = 0.f;
#pragma unroll
        for (int c = 0; c < 16; c++) O[i][c] = 0.f;
    }

    const int n_tiles = qt + 1;
    for (int kt = 0; kt < n_tiles; kt++) {
        const int k0 = kt * BK;
        __syncthreads();

        {
            const float* kbase = k + ((size_t)(b * S_LEN + k0)) * KV_DIM + kvh * HD;
            for (int idx = tid; idx < BK * HD; idx += 128) {
                int r = idx >> 7;
                int d = idx & 127;
                KVs[r * QS_STRIDE + d] = kbase[(size_t)r * KV_DIM + d];
            }
        }
        __syncthreads();

        float s[4][8];
#pragma unroll
        for (int i = 0; i < 4; i++)
#pragma unroll
            for (int j = 0; j < 8; j++) s[i][j] = 0.f;

#pragma unroll 4
        for (int d = 0; d < HD; d++) {
            float qv[4], kv[8];
#pragma unroll
            for (int i = 0; i < 4; i++) qv[i] = Qs[(ty * 4 + i) * QS_STRIDE + d];
#pragma unroll
            for (int j = 0; j < 8; j++) kv[j] = KVs[(tx * 8 + j) * QS_STRIDE + d];
#pragma unroll
            for (int i = 0; i < 4; i++)
#pragma unroll
                for (int j = 0; j < 8; j++)
                    s[i][j] += qv[i] * kv[j];
        }

        if (kt == qt) {
#pragma unroll
            for (int i = 0; i < 4; i++) {
                int qpos = q0 + ty * 4 + i;
#pragma unroll
                for (int j = 0; j < 8; j++) {
                    int kpos = k0 + tx * 8 + j;
                    if (kpos > qpos) s[i][j] = -1e30f;
                }
            }
        }

        float mnew[4], alpha[4];
#pragma unroll
        for (int i = 0; i < 4; i++) {
            float mx = s[i][0];
#pragma unroll
            for (int j = 1; j < 8; j++) mx = fmaxf(mx, s[i][j]);
#pragma unroll
            for (int off = 1; off < 8; off <<= 1)
                mx = fmaxf(mx, __shfl_xor_sync(0xffffffffu, mx, off));
            mnew[i] = fmaxf(m_i[i], mx);
            alpha[i] = expf(m_i[i] - mnew[i]);
            float ps = 0.f;
#pragma unroll
            for (int j = 0; j < 8; j++) {
                float p = expf(s[i][j] - mnew[i]);
                s[i][j] = p;
                ps += p;
            }
#pragma unroll
            for (int off = 1; off < 8; off <<= 1)
                ps += __shfl_xor_sync(0xffffffffu, ps, off);
            l_i[i] = l_i[i] * alpha[i] + ps;
            m_i[i] = mnew[i];
#pragma unroll
            for (int c = 0; c < 16; c++) O[i][c] *= alpha[i];
        }

#pragma unroll
        for (int j = 0; j < 8; j++)
#pragma unroll
            for (int i = 0; i < 4; i++)
                Ps[(tx * 8 + j) * PS_STRIDE + (ty * 4 + i)] = s[i][j];
        __syncthreads();

        {
            const float* vbase = v + ((size_t)(b * S_LEN + k0)) * KV_DIM + kvh * HD;
            for (int idx = tid; idx < BK * HD; idx += 128) {
                int r = idx >> 7;
                int d = idx & 127;
                KVs[r * 128 + d] = vbase[(size_t)r * KV_DIM + d];
            }
        }
        __syncthreads();

#pragma unroll 2
        for (int j = 0; j < BK; j++) {
            float pv[4];
#pragma unroll
            for (int i = 0; i < 4; i++) pv[i] = Ps[j * PS_STRIDE + ty * 4 + i];
#pragma unroll
            for (int g = 0; g < 4; g++) {
                float4 vv = *(const float4*)(&KVs[j * 128 + g * 32 + tx * 4]);
#pragma unroll
                for (int i = 0; i < 4; i++) {
                    O[i][g * 4 + 0] += pv[i] * vv.x;
                    O[i][g * 4 + 1] += pv[i] * vv.y;
                    O[i][g * 4 + 2] += pv[i] * vv.z;
                    O[i][g * 4 + 3] += pv[i] * vv.w;
                }
            }
        }
    }

#pragma unroll
    for (int i = 0; i < 4; i++) {
        float inv_l = 1.f / l_i[i];
        int t = b * S_LEN + q0 + ty * 4 + i;
        float* orow = o + (size_t)t * DIM + h * HD;
#pragma unroll
        for (int g = 0; g < 4; g++) {
            float4 st = make_float4(O[i][g * 4 + 0] * inv_l, O[i][g * 4 + 1] * inv_l,
                                    O[i][g * 4 + 2] * inv_l, O[i][g * 4 + 3] * inv_l);
            *(float4*)(&orow[g * 32 + tx * 4]) = st;
        }
    }
}

// ---------------- launcher ----------------
extern "C" void kernel_launch(void* const* d_in, const int* in_sizes, int n_in,
                              void* d_out, int out_size)
{
    const float* x  = (const float*)d_in[0];
    const float* wq = (const float*)d_in[1];
    const float* wk = (const float*)d_in[2];
    const float* wv = (const float*)d_in[3];
    const float* wo = (const float*)d_in[4];
    const int* positions = (const int*)d_in[7];
    float* out = (float*)d_out;

    float *pq, *pk, *pv, *pa;
    cudaGetSymbolAddress((void**)&pq, g_q);
    cudaGetSymbolAddress((void**)&pk, g_k);
    cudaGetSymbolAddress((void**)&pv, g_v);
    cudaGetSymbolAddress((void**)&pa, g_attn);

    __nv_bfloat16 *xh, *xl, *ah, *al;
    __nv_bfloat16 *wqh, *wql, *wkh, *wkl, *wvh, *wvl, *woh, *wol;
    cudaGetSymbolAddress((void**)&xh, g_xh);
    cudaGetSymbolAddress((void**)&xl, g_xl);
    cudaGetSymbolAddress((void**)&ah, g_ah);
    cudaGetSymbolAddress((void**)&al, g_al);
    cudaGetSymbolAddress((void**)&wqh, g_wqTh);
    cudaGetSymbolAddress((void**)&wql, g_wqTl);
    cudaGetSymbolAddress((void**)&wkh, g_wkTh);
    cudaGetSymbolAddress((void**)&wkl, g_wkTl);
    cudaGetSymbolAddress((void**)&wvh, g_wvTh);
    cudaGetSymbolAddress((void**)&wvl, g_wvTl);
    cudaGetSymbolAddress((void**)&woh, g_woTh);
    cudaGetSymbolAddress((void**)&wol, g_woTl);

    cudaFuncSetAttribute(gemm_mma, cudaFuncAttributeMaxDynamicSharedMemorySize, GT_TOTAL);

    // split x, transpose+split weights
    {
        int total = T_TOK * DIM;
        convert_split<<<(total + 255) / 256, 256>>>(x, xh, xl, total);
        transpose_convert<<<dim3(DIM / 32,    DIM / 32), 256>>>(wq, wqh, wql, DIM, DIM);
        transpose_convert<<<dim3(KV_DIM / 32, DIM / 32), 256>>>(wk, wkh, wkl, DIM, KV_DIM);
        transpose_convert<<<dim3(KV_DIM / 32, DIM / 32), 256>>>(wv, wvh, wvl, DIM, KV_DIM);
        transpose_convert<<<dim3(DIM / 32,    DIM / 32), 256>>>(wo, woh, wol, DIM, DIM);
    }

    // QKV projections on tensor cores
    gemm_mma<<<dim3(DIM / 128,    T_TOK / 128), 256, GT_TOTAL>>>(xh, xl, wqh, wql, pq, DIM,    DIM);
    gemm_mma<<<dim3(KV_DIM / 128, T_TOK / 128), 256, GT_TOTAL>>>(xh, xl, wkh, wkl, pk, KV_DIM, DIM);
    gemm_mma<<<dim3(KV_DIM / 128, T_TOK / 128), 256, GT_TOTAL>>>(xh, xl, wvh, wvl, pv, KV_DIM, DIM);

    // RoPE on q and k
    {
        int total_q = T_TOK * NH * (HD / 2);
        int total_k = T_TOK * NKV * (HD / 2);
        rope_kernel<<<(total_q + 255) / 256, 256>>>(pq, positions, NH,  total_q);
        rope_kernel<<<(total_k + 255) / 256, 256>>>(pk, positions, NKV, total_k);
    }

    // attention
    {
        size_t smem = ATT_SMEM_FLOATS * sizeof(float);
        cudaFuncSetAttribute(attn_kernel, cudaFuncAttributeMaxDynamicSharedMemorySize, (int)smem);
        attn_kernel<<<dim3(S_LEN / BQ, NH, B_SZ), 128, smem>>>(pq, pk, pv, pa);
    }

    // output projection
    {
        int total = T_TOK * DIM;
        convert_split<<<(total + 255) / 256, 256>>>(pa, ah, al, total);
        gemm_mma<<<dim3(DIM / 128, T_TOK / 128), 256, GT_TOTAL>>>(ah, al, woh, wol, out, DIM, DIM);
    }
}

// round 7
// speedup vs baseline: 1.8093x; 1.2829x over previous
#include <cuda_runtime.h>
#include <cuda_bf16.h>
#include <cstdint>
#include <math.h>

// ---------------- problem constants ----------------
#define T_TOK   8192
#define DIM     2048
#define NH      16
#define NKV     8
#define HD      128
#define S_LEN   1024
#define B_SZ    8
#define KV_DIM  1024      // NKV * HD
#define N_REP   2

// ---------------- scratch ----------------
__device__ float g_q[T_TOK * DIM];
__device__ float g_k[T_TOK * KV_DIM];
__device__ float g_v[T_TOK * KV_DIM];

// bf16 hi/lo splits
__device__ __nv_bfloat16 g_xh[T_TOK * DIM];   // x split, then reused as q split (hi)
__device__ __nv_bfloat16 g_xl[T_TOK * DIM];   //                                (lo)
__device__ __nv_bfloat16 g_ah[T_TOK * DIM];   // attn out split hi
__device__ __nv_bfloat16 g_al[T_TOK * DIM];   // attn out split lo
__device__ __nv_bfloat16 g_kh[T_TOK * KV_DIM];
__device__ __nv_bfloat16 g_kl[T_TOK * KV_DIM];
__device__ __nv_bfloat16 g_vh[T_TOK * KV_DIM];
__device__ __nv_bfloat16 g_vl[T_TOK * KV_DIM];
// transposed bf16 hi/lo weights: [N, K] row-major (K contiguous)
__device__ __nv_bfloat16 g_wqTh[DIM * DIM];
__device__ __nv_bfloat16 g_wqTl[DIM * DIM];
__device__ __nv_bfloat16 g_wkTh[KV_DIM * DIM];
__device__ __nv_bfloat16 g_wkTl[KV_DIM * DIM];
__device__ __nv_bfloat16 g_wvTh[KV_DIM * DIM];
__device__ __nv_bfloat16 g_wvTl[KV_DIM * DIM];
__device__ __nv_bfloat16 g_woTh[DIM * DIM];
__device__ __nv_bfloat16 g_woTl[DIM * DIM];

// ================= low-level helpers (sm_80-class PTX only) =================
__device__ __forceinline__ uint32_t smem_to_u32(const void* smem_ptr) {
    uint32_t addr;
    asm("{ .reg .u64 tmp; cvta.to.shared.u64 tmp, %1; cvt.u32.u64 %0, tmp; }"
        : "=r"(addr) : "l"(smem_ptr));
    return addr;
}

#define CP_ASYNC16(dst_u32, src_ptr) \
    asm volatile("cp.async.cg.shared.global [%0], [%1], 16;" \
                 :: "r"(dst_u32), "l"(src_ptr) : "memory")
#define CP_COMMIT() asm volatile("cp.async.commit_group;" ::: "memory")
#define CP_WAIT0()  asm volatile("cp.async.wait_group 0;" ::: "memory")
#define CP_WAIT1()  asm volatile("cp.async.wait_group 1;" ::: "memory")

__device__ __forceinline__ void ldm_x4(uint32_t* r, uint32_t addr) {
    asm volatile("ldmatrix.sync.aligned.m8n8.x4.shared.b16 {%0,%1,%2,%3}, [%4];"
                 : "=r"(r[0]), "=r"(r[1]), "=r"(r[2]), "=r"(r[3]) : "r"(addr));
}
__device__ __forceinline__ void ldm_x2(uint32_t* r, uint32_t addr) {
    asm volatile("ldmatrix.sync.aligned.m8n8.x2.shared.b16 {%0,%1}, [%2];"
                 : "=r"(r[0]), "=r"(r[1]) : "r"(addr));
}
__device__ __forceinline__ void ldm_x2_trans(uint32_t* r, uint32_t addr) {
    asm volatile("ldmatrix.sync.aligned.m8n8.x2.trans.shared.b16 {%0,%1}, [%2];"
                 : "=r"(r[0]), "=r"(r[1]) : "r"(addr));
}
__device__ __forceinline__ void mma16816(float* c, const uint32_t* a, const uint32_t* b) {
    asm volatile("mma.sync.aligned.m16n8k16.row.col.f32.bf16.bf16.f32 "
                 "{%0,%1,%2,%3}, {%4,%5,%6,%7}, {%8,%9}, {%0,%1,%2,%3};"
                 : "+f"(c[0]), "+f"(c[1]), "+f"(c[2]), "+f"(c[3])
                 : "r"(a[0]), "r"(a[1]), "r"(a[2]), "r"(a[3]), "r"(b[0]), "r"(b[1]));
}
// pack two fp32 into bf16x2 word: low half = first arg, high half = second
__device__ __forceinline__ uint32_t packbf(float lo, float hi) {
    uint32_t r;
    asm("cvt.rn.bf16x2.f32 %0, %1, %2;" : "=r"(r) : "f"(hi), "f"(lo));
    return r;
}

// ================= bf16x3 mma.sync GEMM =================
// C[M,N] = A[M,K] @ W[K,N];  A as (Ah+Al) bf16 [M,K] K-major,
// W^T as (Bh+Bl) bf16 [N,K] K-major.  CTA tile 128x128, K-tile 32, 2-stage cp.async.
#define GT_ROWB   80
#define GT_TILE   (128 * GT_ROWB)          // 10240 B
#define GT_STAGE  (4 * GT_TILE)            // 40960 B
#define GT_TOTAL  (2 * GT_STAGE)           // 81920 B

__global__ __launch_bounds__(256, 2)
void gemm_mma(const __nv_bfloat16* __restrict__ Ah, const __nv_bfloat16* __restrict__ Al,
              const __nv_bfloat16* __restrict__ Bh, const __nv_bfloat16* __restrict__ Bl,
              float* __restrict__ C, int Ncols, int K)
{
    extern __shared__ char smc[];
    const uint32_t sbase = smem_to_u32(smc);

    const int tid  = threadIdx.x;
    const int lane = tid & 31;
    const int wid  = tid >> 5;
    const int bx = blockIdx.x;
    const int by = blockIdx.y;
    const int m0 = (wid & 1) * 64;
    const int n0 = (wid >> 1) * 32;

    const int ch0 = tid;
    const int ch1 = tid + 256;
    const int r0c = ch0 >> 2, c0c = ch0 & 3;
    const int r1c = ch1 >> 2, c1c = ch1 & 3;

    const size_t ga0 = (size_t)(by * 128 + r0c) * K + c0c * 8;
    const size_t ga1 = (size_t)(by * 128 + r1c) * K + c1c * 8;
    const size_t gb0 = (size_t)(bx * 128 + r0c) * K + c0c * 8;
    const size_t gb1 = (size_t)(bx * 128 + r1c) * K + c1c * 8;
    const uint32_t so0 = r0c * GT_ROWB + c0c * 16;
    const uint32_t so1 = r1c * GT_ROWB + c1c * 16;

    float acc[4][4][4];
#pragma unroll
    for (int i = 0; i < 4; i++)
#pragma unroll
        for (int j = 0; j < 4; j++)
#pragma unroll
            for (int e = 0; e < 4; e++) acc[i][j][e] = 0.f;

    const int n_kt = K >> 5;

    const uint32_t a_row = (uint32_t)(m0 + (lane & 15));
    const uint32_t a_coloff = (uint32_t)((lane >> 4) * 16);
    const uint32_t b_row = (uint32_t)(n0 + (lane & 7));
    const uint32_t b_coloff = (uint32_t)(((lane >> 3) & 1) * 16);

    {
        const uint32_t st = sbase;
        CP_ASYNC16(st + 0 * GT_TILE + so0, Ah + ga0);
        CP_ASYNC16(st + 0 * GT_TILE + so1, Ah + ga1);
        CP_ASYNC16(st + 1 * GT_TILE + so0, Al + ga0);
        CP_ASYNC16(st + 1 * GT_TILE + so1, Al + ga1);
        CP_ASYNC16(st + 2 * GT_TILE + so0, Bh + gb0);
        CP_ASYNC16(st + 2 * GT_TILE + so1, Bh + gb1);
        CP_ASYNC16(st + 3 * GT_TILE + so0, Bl + gb0);
        CP_ASYNC16(st + 3 * GT_TILE + so1, Bl + gb1);
        CP_COMMIT();
    }

    for (int kt = 0; kt < n_kt; kt++) {
        const int cur = kt & 1;
        if (kt + 1 < n_kt) {
            const uint32_t st = sbase + (cur ^ 1) * GT_STAGE;
            const size_t ko = (size_t)(kt + 1) * 32;
            CP_ASYNC16(st + 0 * GT_TILE + so0, Ah + ga0 + ko);
            CP_ASYNC16(st + 0 * GT_TILE + so1, Ah + ga1 + ko);
            CP_ASYNC16(st + 1 * GT_TILE + so0, Al + ga0 + ko);
            CP_ASYNC16(st + 1 * GT_TILE + so1, Al + ga1 + ko);
            CP_ASYNC16(st + 2 * GT_TILE + so0, Bh + gb0 + ko);
            CP_ASYNC16(st + 2 * GT_TILE + so1, Bh + gb1 + ko);
            CP_ASYNC16(st + 3 * GT_TILE + so0, Bl + gb0 + ko);
            CP_ASYNC16(st + 3 * GT_TILE + so1, Bl + gb1 + ko);
            CP_COMMIT();
            CP_WAIT1();
        } else {
            CP_WAIT0();
        }
        __syncthreads();

        const uint32_t st = sbase + cur * GT_STAGE;
        const uint32_t sAh = st;
        const uint32_t sAl = st + 1 * GT_TILE;
        const uint32_t sBh = st + 2 * GT_TILE;
        const uint32_t sBl = st + 3 * GT_TILE;

#pragma unroll
        for (int ks = 0; ks < 2; ks++) {
            const uint32_t kb = ks * 32;
            uint32_t af[4][4], bf[4][2];
            // pass 1: Ahi * Bhi
#pragma unroll
            for (int mt = 0; mt < 4; mt++)
                ldm_x4(af[mt], sAh + (a_row + mt * 16) * GT_ROWB + kb + a_coloff);
#pragma unroll
            for (int nt = 0; nt < 4; nt++)
                ldm_x2(bf[nt], sBh + (b_row + nt * 8) * GT_ROWB + kb + b_coloff);
#pragma unroll
            for (int mt = 0; mt < 4; mt++)
#pragma unroll
                for (int nt = 0; nt < 4; nt++)
                    mma16816(acc[mt][nt], af[mt], bf[nt]);
            // pass 2: Ahi * Blo (overwrite B frags)
#pragma unroll
            for (int nt = 0; nt < 4; nt++)
                ldm_x2(bf[nt], sBl + (b_row + nt * 8) * GT_ROWB + kb + b_coloff);
#pragma unroll
            for (int mt = 0; mt < 4; mt++)
#pragma unroll
                for (int nt = 0; nt < 4; nt++)
                    mma16816(acc[mt][nt], af[mt], bf[nt]);
            // pass 3: Alo * Bhi (overwrite A and B frags)
#pragma unroll
            for (int mt = 0; mt < 4; mt++)
                ldm_x4(af[mt], sAl + (a_row + mt * 16) * GT_ROWB + kb + a_coloff);
#pragma unroll
            for (int nt = 0; nt < 4; nt++)
                ldm_x2(bf[nt], sBh + (b_row + nt * 8) * GT_ROWB + kb + b_coloff);
#pragma unroll
            for (int mt = 0; mt < 4; mt++)
#pragma unroll
                for (int nt = 0; nt < 4; nt++)
                    mma16816(acc[mt][nt], af[mt], bf[nt]);
        }
        __syncthreads();
    }

    const int g  = lane >> 2;
    const int tg = (lane & 3) * 2;
#pragma unroll
    for (int mt = 0; mt < 4; mt++) {
        const int r = by * 128 + m0 + mt * 16 + g;
#pragma unroll
        for (int nt = 0; nt < 4; nt++) {
            const int cc = bx * 128 + n0 + nt * 8 + tg;
            *(float2*)(C + (size_t)r * Ncols + cc) =
                make_float2(acc[mt][nt][0], acc[mt][nt][1]);
            *(float2*)(C + (size_t)(r + 8) * Ncols + cc) =
                make_float2(acc[mt][nt][2], acc[mt][nt][3]);
        }
    }
}

// ---------------- fp32 -> bf16 hi/lo split ----------------
__global__ __launch_bounds__(256)
void convert_split(const float* __restrict__ X, __nv_bfloat16* __restrict__ H,
                   __nv_bfloat16* __restrict__ L, int total)
{
    int i = blockIdx.x * blockDim.x + threadIdx.x;
    if (i >= total) return;
    float v = X[i];
    __nv_bfloat16 h = __float2bfloat16(v);
    H[i] = h;
    L[i] = __float2bfloat16(v - __bfloat162float(h));
}

// ---------------- W[K,N] -> W^T hi/lo bf16 [N,K] ----------------
__global__ __launch_bounds__(256)
void transpose_convert(const float* __restrict__ W, __nv_bfloat16* __restrict__ Th,
                       __nv_bfloat16* __restrict__ Tl, int K, int N)
{
    __shared__ float t[32][33];
    int n0 = blockIdx.x * 32, k0 = blockIdx.y * 32;
    int tx = threadIdx.x & 31, ty = threadIdx.x >> 5;
#pragma unroll
    for (int j = 0; j < 4; j++)
        t[ty + j * 8][tx] = W[(size_t)(k0 + ty + j * 8) * N + n0 + tx];
    __syncthreads();
#pragma unroll
    for (int j = 0; j < 4; j++) {
        float v = t[tx][ty + j * 8];
        __nv_bfloat16 h = __float2bfloat16(v);
        __nv_bfloat16 l = __float2bfloat16(v - __bfloat162float(h));
        size_t o = (size_t)(n0 + ty + j * 8) * K + k0 + tx;
        Th[o] = h;
        Tl[o] = l;
    }
}

// ---------------- RoPE + bf16 hi/lo split ----------------
__global__ __launch_bounds__(256)
void rope_split(const float* __restrict__ src, const int* __restrict__ positions,
                __nv_bfloat16* __restrict__ H, __nv_bfloat16* __restrict__ L,
                int n_heads, float scale, int total)
{
    int idx = blockIdx.x * blockDim.x + threadIdx.x;
    if (idx >= total) return;
    int pair = idx & 63;
    int h    = (idx >> 6) % n_heads;
    int t    = idx / (64 * n_heads);
    double inv = pow(10000.0, -(double)(2 * pair) / 128.0);
    double ang = (double)positions[t] * inv;
    float c = (float)cos(ang);
    float s = (float)sin(ang);
    size_t o = (size_t)t * (n_heads * HD) + h * HD + 2 * pair;
    float xr = src[o], xi = src[o + 1];
    float vr = (xr * c - xi * s) * scale;
    float vi = (xr * s + xi * c) * scale;
    __nv_bfloat16 hr = __float2bfloat16(vr);
    __nv_bfloat16 hi = __float2bfloat16(vi);
    H[o]     = hr;
    H[o + 1] = hi;
    L[o]     = __float2bfloat16(vr - __bfloat162float(hr));
    L[o + 1] = __float2bfloat16(vi - __bfloat162float(hi));
}

// ================= mma.sync flash attention (causal, GQA rep=2) =================
// grid (S/64, NH, B), 128 threads (4 warps; warp w owns query rows w*16..w*16+15)
// smem tiles: Qh, Ql, Kh, Kl, Vh, Vl each [64 rows][128 bf16], row stride 272 B
#define AT_ROWB 272
#define AT_TILE (64 * AT_ROWB)
#define AT_SMEM (6 * AT_TILE)   // 104448 B -> 2 CTAs/SM

__global__ __launch_bounds__(128)
void attn_mma(const __nv_bfloat16* __restrict__ qh, const __nv_bfloat16* __restrict__ ql,
              const __nv_bfloat16* __restrict__ kh, const __nv_bfloat16* __restrict__ kl,
              const __nv_bfloat16* __restrict__ vhp, const __nv_bfloat16* __restrict__ vlp,
              __nv_bfloat16* __restrict__ oh, __nv_bfloat16* __restrict__ ol)
{
    extern __shared__ char smb[];
    const uint32_t sb  = smem_to_u32(smb);
    const uint32_t sQh = sb;
    const uint32_t sQl = sb + AT_TILE;
    const uint32_t sKh = sb + 2 * AT_TILE;
    const uint32_t sKl = sb + 3 * AT_TILE;
    const uint32_t sVh = sb + 4 * AT_TILE;
    const uint32_t sVl = sb + 5 * AT_TILE;

    const int tid  = threadIdx.x;
    const int lane = tid & 31;
    const int wid  = tid >> 5;
    const int qt = blockIdx.x, h = blockIdx.y, b = blockIdx.z;
    const int kvh = h >> 1;
    const int q0 = qt * 64;
    const int m0 = wid * 16;
    const int g  = lane >> 2;
    const int tg = lane & 3;

    // --- Q tiles (hi+lo), loaded once ---
    {
        const __nv_bfloat16* srcH = qh + (size_t)(b * S_LEN + q0) * DIM + h * HD;
        const __nv_bfloat16* srcL = ql + (size_t)(b * S_LEN + q0) * DIM + h * HD;
        for (int c = tid; c < 1024; c += 128) {
            int r = c >> 4, cc = c & 15;
            CP_ASYNC16(sQh + r * AT_ROWB + cc * 16, srcH + (size_t)r * DIM + cc * 8);
            CP_ASYNC16(sQl + r * AT_ROWB + cc * 16, srcL + (size_t)r * DIM + cc * 8);
        }
        CP_COMMIT();
    }

    float oacc[16][4];
#pragma unroll
    for (int nt = 0; nt < 16; nt++)
#pragma unroll
        for (int e = 0; e < 4; e++) oacc[nt][e] = 0.f;
    float mst0 = -1e30f, mst1 = -1e30f, lst0 = 0.f, lst1 = 0.f;

    const uint32_t qa_off = (uint32_t)((m0 + (lane & 15)) * AT_ROWB + (lane >> 4) * 16);
    const uint32_t kb_row = (uint32_t)((lane & 7) * AT_ROWB + ((lane >> 3) & 1) * 16);
    const uint32_t v_row  = (uint32_t)((lane & 15) * AT_ROWB);

    for (int kt = 0; kt <= qt; kt++) {
        // --- load K (hi+lo) and V (hi+lo) tiles ---
        {
            const size_t base = (size_t)(b * S_LEN + kt * 64) * KV_DIM + kvh * HD;
            const __nv_bfloat16* pKh = kh + base;
            const __nv_bfloat16* pKl = kl + base;
            const __nv_bfloat16* pVh = vhp + base;
            const __nv_bfloat16* pVl = vlp + base;
            for (int c = tid; c < 1024; c += 128) {
                int r = c >> 4, cc = c & 15;
                CP_ASYNC16(sKh + r * AT_ROWB + cc * 16, pKh + (size_t)r * KV_DIM + cc * 8);
                CP_ASYNC16(sKl + r * AT_ROWB + cc * 16, pKl + (size_t)r * KV_DIM + cc * 8);
                CP_ASYNC16(sVh + r * AT_ROWB + cc * 16, pVh + (size_t)r * KV_DIM + cc * 8);
                CP_ASYNC16(sVl + r * AT_ROWB + cc * 16, pVl + (size_t)r * KV_DIM + cc * 8);
            }
            CP_COMMIT();
            CP_WAIT0();
        }
        __syncthreads();

        // --- S = Q.K^T, bf16 3-pass ---
        float sacc[8][4];
#pragma unroll
        for (int j = 0; j < 8; j++)
#pragma unroll
            for (int e = 0; e < 4; e++) sacc[j][e] = 0.f;

#pragma unroll
        for (int kk = 0; kk < 8; kk++) {
            uint32_t qfh[4], qfl[4], kf[2];
            ldm_x4(qfh, sQh + qa_off + kk * 32);
            ldm_x4(qfl, sQl + qa_off + kk * 32);
#pragma unroll
            for (int j = 0; j < 8; j++) {
                ldm_x2(kf, sKh + j * 8 * AT_ROWB + kb_row + kk * 32);
                mma16816(sacc[j], qfh, kf);
                mma16816(sacc[j], qfl, kf);
            }
        }
#pragma unroll
        for (int kk = 0; kk < 8; kk++) {
            uint32_t qfh[4], kf[2];
            ldm_x4(qfh, sQh + qa_off + kk * 32);
#pragma unroll
            for (int j = 0; j < 8; j++) {
                ldm_x2(kf, sKl + j * 8 * AT_ROWB + kb_row + kk * 32);
                mma16816(sacc[j], qfh, kf);
            }
        }

        // --- causal mask (diagonal tile only) ---
        if (kt == qt) {
            const int r0l = m0 + g, r1l = m0 + g + 8;
#pragma unroll
            for (int j = 0; j < 8; j++) {
                const int c0 = j * 8 + tg * 2;
                if (c0     > r0l) sacc[j][0] = -1e30f;
                if (c0 + 1 > r0l) sacc[j][1] = -1e30f;
                if (c0     > r1l) sacc[j][2] = -1e30f;
                if (c0 + 1 > r1l) sacc[j][3] = -1e30f;
            }
        }

        // --- online softmax ---
        float mx0 = -1e30f, mx1 = -1e30f;
#pragma unroll
        for (int j = 0; j < 8; j++) {
            mx0 = fmaxf(mx0, fmaxf(sacc[j][0], sacc[j][1]));
            mx1 = fmaxf(mx1, fmaxf(sacc[j][2], sacc[j][3]));
        }
        mx0 = fmaxf(mx0, __shfl_xor_sync(0xffffffffu, mx0, 1));
        mx0 = fmaxf(mx0, __shfl_xor_sync(0xffffffffu, mx0, 2));
        mx1 = fmaxf(mx1, __shfl_xor_sync(0xffffffffu, mx1, 1));
        mx1 = fmaxf(mx1, __shfl_xor_sync(0xffffffffu, mx1, 2));
        const float nm0 = fmaxf(mst0, mx0);
        const float nm1 = fmaxf(mst1, mx1);
        const float a0 = expf(mst0 - nm0);
        const float a1 = expf(mst1 - nm1);
        mst0 = nm0; mst1 = nm1;
        float sum0 = 0.f, sum1 = 0.f;
#pragma unroll
        for (int j = 0; j < 8; j++) {
            sacc[j][0] = expf(sacc[j][0] - nm0);
            sacc[j][1] = expf(sacc[j][1] - nm0);
            sacc[j][2] = expf(sacc[j][2] - nm1);
            sacc[j][3] = expf(sacc[j][3] - nm1);
            sum0 += sacc[j][0] + sacc[j][1];
            sum1 += sacc[j][2] + sacc[j][3];
        }
        sum0 += __shfl_xor_sync(0xffffffffu, sum0, 1);
        sum0 += __shfl_xor_sync(0xffffffffu, sum0, 2);
        sum1 += __shfl_xor_sync(0xffffffffu, sum1, 1);
        sum1 += __shfl_xor_sync(0xffffffffu, sum1, 2);
        lst0 = lst0 * a0 + sum0;
        lst1 = lst1 * a1 + sum1;
#pragma unroll
        for (int nt = 0; nt < 16; nt++) {
            oacc[nt][0] *= a0; oacc[nt][1] *= a0;
            oacc[nt][2] *= a1; oacc[nt][3] *= a1;
        }

        // --- O += P.V with error compensation: Ph.Vh + Ph.Vl + Pl.Vh ---
#pragma unroll
        for (int jk = 0; jk < 4; jk++) {
            uint32_t pfh[4], pfl[4];
#pragma unroll
            for (int q = 0; q < 2; q++) {       // two k8 sub-cols of the P fragment
                const int j = 2 * jk + q;
#pragma unroll
                for (int pr = 0; pr < 2; pr++) { // fragment row pairs (rows g / g+8)
                    float p0 = sacc[j][2 * pr], p1 = sacc[j][2 * pr + 1];
                    __nv_bfloat16 b0 = __float2bfloat16(p0);
                    __nv_bfloat16 b1 = __float2bfloat16(p1);
                    pfh[2 * q + pr] = ((uint32_t)__bfloat16_as_ushort(b1) << 16) |
                                      __bfloat16_as_ushort(b0);
                    pfl[2 * q + pr] = packbf(p0 - __bfloat162float(b0),
                                             p1 - __bfloat162float(b1));
                }
            }
            const uint32_t vbase = jk * 16 * AT_ROWB + v_row;
#pragma unroll
            for (int nt = 0; nt < 16; nt++) {
                uint32_t vfh[2], vfl[2];
                ldm_x2_trans(vfh, sVh + vbase + nt * 16);
                ldm_x2_trans(vfl, sVl + vbase + nt * 16);
                mma16816(oacc[nt], pfh, vfh);
                mma16816(oacc[nt], pfh, vfl);
                mma16816(oacc[nt], pfl, vfh);
            }
        }
        __syncthreads();   // all warps done with K/V smem before next tile's cp.async
    }

    // --- epilogue: normalize, hi/lo split, store bf16 ---
    const float inv0 = 1.f / lst0;
    const float inv1 = 1.f / lst1;
    const size_t r0g = (size_t)(b * S_LEN + q0 + m0 + g);
    const size_t r1g = r0g + 8;
    const int colb = h * HD + tg * 2;
#pragma unroll
    for (int nt = 0; nt < 16; nt++) {
        float v00 = oacc[nt][0] * inv0, v01 = oacc[nt][1] * inv0;
        float v10 = oacc[nt][2] * inv1, v11 = oacc[nt][3] * inv1;
        __nv_bfloat16 h00 = __float2bfloat16(v00), h01 = __float2bfloat16(v01);
        __nv_bfloat16 h10 = __float2bfloat16(v10), h11 = __float2bfloat16(v11);
        float l00 = v00 - __bfloat162float(h00), l01 = v01 - __bfloat162float(h01);
        float l10 = v10 - __bfloat162float(h10), l11 = v11 - __bfloat162float(h11);
        uint32_t hw0 = ((uint32_t)__bfloat16_as_ushort(h01) << 16) | __bfloat16_as_ushort(h00);
        uint32_t hw1 = ((uint32_t)__bfloat16_as_ushort(h11) << 16) | __bfloat16_as_ushort(h10);
        uint32_t lw0 = packbf(l00, l01);
        uint32_t lw1 = packbf(l10, l11);
        const int cc = colb + nt * 8;
        *(uint32_t*)(oh + r0g * DIM + cc) = hw0;
        *(uint32_t*)(ol + r0g * DIM + cc) = lw0;
        *(uint32_t*)(oh + r1g * DIM + cc) = hw1;
        *(uint32_t*)(ol + r1g * DIM + cc) = lw1;
    }
}

// ---------------- launcher ----------------
extern "C" void kernel_launch(void* const* d_in, const int* in_sizes, int n_in,
                              void* d_out, int out_size)
{
    const float* x  = (const float*)d_in[0];
    const float* wq = (const float*)d_in[1];
    const float* wk = (const float*)d_in[2];
    const float* wv = (const float*)d_in[3];
    const float* wo = (const float*)d_in[4];
    const int* positions = (const int*)d_in[7];
    float* out = (float*)d_out;

    float *pq, *pk, *pv;
    cudaGetSymbolAddress((void**)&pq, g_q);
    cudaGetSymbolAddress((void**)&pk, g_k);
    cudaGetSymbolAddress((void**)&pv, g_v);

    __nv_bfloat16 *xh, *xl, *ah, *al, *pkh, *pkl, *pvh, *pvl;
    __nv_bfloat16 *wqh, *wql, *wkh, *wkl, *wvh, *wvl, *woh, *wol;
    cudaGetSymbolAddress((void**)&xh, g_xh);
    cudaGetSymbolAddress((void**)&xl, g_xl);
    cudaGetSymbolAddress((void**)&ah, g_ah);
    cudaGetSymbolAddress((void**)&al, g_al);
    cudaGetSymbolAddress((void**)&pkh, g_kh);
    cudaGetSymbolAddress((void**)&pkl, g_kl);
    cudaGetSymbolAddress((void**)&pvh, g_vh);
    cudaGetSymbolAddress((void**)&pvl, g_vl);
    cudaGetSymbolAddress((void**)&wqh, g_wqTh);
    cudaGetSymbolAddress((void**)&wql, g_wqTl);
    cudaGetSymbolAddress((void**)&wkh, g_wkTh);
    cudaGetSymbolAddress((void**)&wkl, g_wkTl);
    cudaGetSymbolAddress((void**)&wvh, g_wvTh);
    cudaGetSymbolAddress((void**)&wvl, g_wvTl);
    cudaGetSymbolAddress((void**)&woh, g_woTh);
    cudaGetSymbolAddress((void**)&wol, g_woTl);

    cudaFuncSetAttribute(gemm_mma, cudaFuncAttributeMaxDynamicSharedMemorySize, GT_TOTAL);
    cudaFuncSetAttribute(attn_mma, cudaFuncAttributeMaxDynamicSharedMemorySize, AT_SMEM);

    // split x, transpose+split weights
    {
        int total = T_TOK * DIM;
        convert_split<<<(total + 255) / 256, 256>>>(x, xh, xl, total);
        transpose_convert<<<dim3(DIM / 32,    DIM / 32), 256>>>(wq, wqh, wql, DIM, DIM);
        transpose_convert<<<dim3(KV_DIM / 32, DIM / 32), 256>>>(wk, wkh, wkl, DIM, KV_DIM);
        transpose_convert<<<dim3(KV_DIM / 32, DIM / 32), 256>>>(wv, wvh, wvl, DIM, KV_DIM);
        transpose_convert<<<dim3(DIM / 32,    DIM / 32), 256>>>(wo, woh, wol, DIM, DIM);
    }

    // QKV projections on tensor cores (fp32 outputs)
    gemm_mma<<<dim3(DIM / 128,    T_TOK / 128), 256, GT_TOTAL>>>(xh, xl, wqh, wql, pq, DIM,    DIM);
    gemm_mma<<<dim3(KV_DIM / 128, T_TOK / 128), 256, GT_TOTAL>>>(xh, xl, wkh, wkl, pk, KV_DIM, DIM);
    gemm_mma<<<dim3(KV_DIM / 128, T_TOK / 128), 256, GT_TOTAL>>>(xh, xl, wvh, wvl, pv, KV_DIM, DIM);

    // RoPE + split (q scaled by 1/sqrt(HD); x splits reused as q splits), V -> hi/lo bf16
    {
        const float scale = 0.08838834764831845f;
        int total_q = T_TOK * NH * (HD / 2);
        int total_k = T_TOK * NKV * (HD / 2);
        rope_split<<<(total_q + 255) / 256, 256>>>(pq, positions, xh, xl, NH,  scale, total_q);
        rope_split<<<(total_k + 255) / 256, 256>>>(pk, positions, pkh, pkl, NKV, 1.0f, total_k);
        int total_v = T_TOK * KV_DIM;
        convert_split<<<(total_v + 255) / 256, 256>>>(pv, pvh, pvl, total_v);
    }

    // flash attention (writes hi/lo bf16 splits of attn output)
    attn_mma<<<dim3(S_LEN / 64, NH, B_SZ), 128, AT_SMEM>>>(xh, xl, pkh, pkl, pvh, pvl, ah, al);

    // output projection
    gemm_mma<<<dim3(DIM / 128, T_TOK / 128), 256, GT_TOTAL>>>(ah, al, woh, wol, out, DIM, DIM);
}